// round 7
// baseline (speedup 1.0000x reference)
#include <cuda_runtime.h>
#include <cuda_bf16.h>

#define NN 100000
#define NE 1600000
#define BN_EPS 1e-5f
#define SCAN_BLK 1024
#define N_SCAN_BLKS ((NN + SCAN_BLK - 1) / SCAN_BLK)   // 98
#define FULL 0xffffffffu
#define CNT_BLKS ((NE + 255) / 256)                     // 6250
#define PROJ_BLKS ((NN + 7) / 8)                        // 12500

// ---------------- scratch (static device memory, no allocs) ----------------
__device__ float g_bufA[NN * 32];     // h buffers (double-buffered)
__device__ float g_bufB[NN * 32];
__device__ float g_stats[5 * 64];     // zero-init; self-cleaned by finalize
__device__ float g_ab[64];            // BN a[32], b[32] (for pool)
__device__ float g_Wap[1024];         // folded Wa' = diag(a)*Wa
__device__ float g_cvec[32];          // c = b @ Wa
__device__ float4 g_pool[64 * 8];     // zeroed by combo each replay
// CSR
__device__ int g_cnt[NN];             // zero-init; self-cleaned by scan_a
__device__ int g_excl[NN];
__device__ int g_bsum[128];
__device__ int g_boff[128];
__device__ int g_rs[NN + 1];
__device__ int g_cur[NN];
__device__ int g_col[NE];

__device__ __forceinline__ void red_add_f32x4(float4* addr, float4 v) {
    asm volatile("red.global.add.v4.f32 [%0], {%1, %2, %3, %4};"
                 :: "l"(addr), "f"(v.x), "f"(v.y), "f"(v.z), "f"(v.w)
                 : "memory");
}

// ---------------- launch 1: count + proj (p = x @ W1a) + zero pool ----------
__global__ __launch_bounds__(256) void combo_kernel(
    const float2* __restrict__ x2, const float* __restrict__ W1a,
    const int* __restrict__ dsts) {
    __shared__ float sW[2048];        // 64x32
    int tid = threadIdx.x;
    if (blockIdx.x < CNT_BLKS) {
        int e = blockIdx.x * 256 + tid;
        if (e < NE) atomicAdd(&g_cnt[dsts[e]], 1);
        if (blockIdx.x == 0) {
            float* p = (float*)g_pool;
            for (int i = tid; i < 64 * 8 * 4; i += 256) p[i] = 0.f;
        }
        return;
    }
    for (int i = tid; i < 2048; i += 256) sW[i] = W1a[i];
    __syncthreads();
    int lane = tid & 31, wid = tid >> 5;
    int node = (blockIdx.x - CNT_BLKS) * 8 + wid;
    if (node >= NN) return;
    float2 xv = x2[(size_t)node * 32 + lane];
    float t = 0.f;
    #pragma unroll
    for (int j = 0; j < 32; j++) {
        float bx = __shfl_sync(FULL, xv.x, j);
        float by = __shfl_sync(FULL, xv.y, j);
        t = fmaf(bx, sW[(2 * j) * 32 + lane], t);
        t = fmaf(by, sW[(2 * j + 1) * 32 + lane], t);
    }
    g_bufA[(size_t)node * 32 + lane] = t;
}

// ---------------- CSR scan (self-cleans g_cnt) ------------------------------
__global__ void scan_a_kernel() {
    __shared__ int wsum[8];
    int base = blockIdx.x * SCAN_BLK + threadIdx.x * 4;
    int v0 = (base + 0 < NN) ? g_cnt[base + 0] : 0;
    int v1 = (base + 1 < NN) ? g_cnt[base + 1] : 0;
    int v2 = (base + 2 < NN) ? g_cnt[base + 2] : 0;
    int v3 = (base + 3 < NN) ? g_cnt[base + 3] : 0;
    if (base + 0 < NN) g_cnt[base + 0] = 0;
    if (base + 1 < NN) g_cnt[base + 1] = 0;
    if (base + 2 < NN) g_cnt[base + 2] = 0;
    if (base + 3 < NN) g_cnt[base + 3] = 0;
    int tsum = v0 + v1 + v2 + v3;
    int lane = threadIdx.x & 31, wid = threadIdx.x >> 5;
    int incl = tsum;
    #pragma unroll
    for (int off = 1; off < 32; off <<= 1) {
        int n = __shfl_up_sync(FULL, incl, off);
        if (lane >= off) incl += n;
    }
    if (lane == 31) wsum[wid] = incl;
    __syncthreads();
    if (wid == 0 && lane < 8) {
        int w = wsum[lane];
        #pragma unroll
        for (int off = 1; off < 8; off <<= 1) {
            int n = __shfl_up_sync(0xffu, w, off);
            if (lane >= off) w += n;
        }
        wsum[lane] = w;
    }
    __syncthreads();
    int off = (wid > 0 ? wsum[wid - 1] : 0) + incl - tsum;
    if (base + 0 < NN) g_excl[base + 0] = off;
    if (base + 1 < NN) g_excl[base + 1] = off + v0;
    if (base + 2 < NN) g_excl[base + 2] = off + v0 + v1;
    if (base + 3 < NN) g_excl[base + 3] = off + v0 + v1 + v2;
    if (threadIdx.x == 0) g_bsum[blockIdx.x] = wsum[7];
}

__global__ void scan_b_kernel() {
    __shared__ int s[128];
    int t = threadIdx.x;
    int orig = (t < N_SCAN_BLKS) ? g_bsum[t] : 0;
    s[t] = orig;
    __syncthreads();
    #pragma unroll
    for (int off = 1; off < 128; off <<= 1) {
        int v = (t >= off) ? s[t - off] : 0;
        __syncthreads();
        s[t] += v;
        __syncthreads();
    }
    if (t < N_SCAN_BLKS) g_boff[t] = s[t] - orig;
}

__global__ void scan_c_kernel() {
    int i = blockIdx.x * blockDim.x + threadIdx.x;
    if (i < NN) {
        int rs = g_excl[i] + g_boff[i / SCAN_BLK];
        g_rs[i] = rs;
        g_cur[i] = rs;
    }
    if (i == 0) g_rs[NN] = NE;
}

__global__ void fill_kernel(const int* __restrict__ srcs,
                            const int* __restrict__ dsts) {
    int e = blockIdx.x * blockDim.x + threadIdx.x;
    if (e >= NE) return;
    int d = dsts[e];
    int pos = atomicAdd(&g_cur[d], 1);
    g_col[pos] = srcs[e];
}

// ---------------- fused layer: gather + MLP + stats -------------------------
// 512 threads = 64 nodes/block, 8 lanes per node (lane c = float4 channel c).
// agg = h[n] + sum h[j];  MLP 8-way parallel per node via width-8 shuffles.
template<bool FIRST>
__global__ __launch_bounds__(512) void layer_kernel(
    const float* __restrict__ Wb, const float* __restrict__ Ba,
    const float* __restrict__ Bb, int layer) {
    __shared__ float sW1[1024];
    __shared__ float sW2[1024];
    __shared__ float sBa[32], sBb[32], sC[32];
    __shared__ float sstat[64];
    int tid = threadIdx.x;
    for (int i = tid; i < 1024; i += 512) {
        if (!FIRST) sW1[i] = g_Wap[i];
        sW2[i] = Wb[i];
    }
    if (tid < 32) {
        sBa[tid] = Ba[tid];
        sBb[tid] = Bb[tid];
        sC[tid] = FIRST ? 0.f : g_cvec[tid];
    }
    if (tid < 64) sstat[tid] = 0.f;
    __syncthreads();

    const float4* fin = (const float4*)((layer & 1) ? g_bufB : g_bufA);
    float4*       fout = (float4*)((layer & 1) ? g_bufA : g_bufB);

    int grp = tid >> 3;             // node within block
    int c   = tid & 7;              // float4 channel
    int node = blockIdx.x * 64 + grp;
    float4 o4 = make_float4(0.f, 0.f, 0.f, 0.f);

    if (node < NN) {
        // ---- gather ----
        int e0 = g_rs[node], e1 = g_rs[node + 1];
        float4 a0 = fin[(size_t)node * 8 + c];
        float4 a1 = make_float4(0.f, 0.f, 0.f, 0.f);
        float4 a2 = make_float4(0.f, 0.f, 0.f, 0.f);
        float4 a3 = make_float4(0.f, 0.f, 0.f, 0.f);
        int e = e0;
        for (; e + 4 <= e1; e += 4) {
            int s0 = __ldg(&g_col[e + 0]);
            int s1 = __ldg(&g_col[e + 1]);
            int s2 = __ldg(&g_col[e + 2]);
            int s3 = __ldg(&g_col[e + 3]);
            float4 v0 = fin[(size_t)s0 * 8 + c];
            float4 v1 = fin[(size_t)s1 * 8 + c];
            float4 v2 = fin[(size_t)s2 * 8 + c];
            float4 v3 = fin[(size_t)s3 * 8 + c];
            a0.x += v0.x; a0.y += v0.y; a0.z += v0.z; a0.w += v0.w;
            a1.x += v1.x; a1.y += v1.y; a1.z += v1.z; a1.w += v1.w;
            a2.x += v2.x; a2.y += v2.y; a2.z += v2.z; a2.w += v2.w;
            a3.x += v3.x; a3.y += v3.y; a3.z += v3.z; a3.w += v3.w;
        }
        for (; e < e1; e++) {
            int s = __ldg(&g_col[e]);
            float4 v = fin[(size_t)s * 8 + c];
            a0.x += v.x; a0.y += v.y; a0.z += v.z; a0.w += v.w;
        }
        float rx = (a0.x + a1.x) + (a2.x + a3.x);
        float ry = (a0.y + a1.y) + (a2.y + a3.y);
        float rz = (a0.z + a1.z) + (a2.z + a3.z);
        float rw = (a0.w + a1.w) + (a2.w + a3.w);

        // ---- GEMM1: t[4c..4c+3] ----
        float t0, t1, t2, t3;
        if (FIRST) {
            t0 = fmaxf(rx + sBa[4 * c + 0], 0.f);
            t1 = fmaxf(ry + sBa[4 * c + 1], 0.f);
            t2 = fmaxf(rz + sBa[4 * c + 2], 0.f);
            t3 = fmaxf(rw + sBa[4 * c + 3], 0.f);
        } else {
            float cnt = (float)(e1 - e0 + 1);
            t0 = fmaf(cnt, sC[4 * c + 0], sBa[4 * c + 0]);
            t1 = fmaf(cnt, sC[4 * c + 1], sBa[4 * c + 1]);
            t2 = fmaf(cnt, sC[4 * c + 2], sBa[4 * c + 2]);
            t3 = fmaf(cnt, sC[4 * c + 3], sBa[4 * c + 3]);
            #pragma unroll
            for (int j = 0; j < 32; j++) {
                float aj;
                switch (j & 3) {
                    case 0: aj = rx; break;
                    case 1: aj = ry; break;
                    case 2: aj = rz; break;
                    default: aj = rw; break;
                }
                aj = __shfl_sync(FULL, aj, j >> 2, 8);
                float4 w = ((const float4*)&sW1[j * 32])[c];
                t0 = fmaf(aj, w.x, t0);
                t1 = fmaf(aj, w.y, t1);
                t2 = fmaf(aj, w.z, t2);
                t3 = fmaf(aj, w.w, t3);
            }
            t0 = fmaxf(t0, 0.f); t1 = fmaxf(t1, 0.f);
            t2 = fmaxf(t2, 0.f); t3 = fmaxf(t3, 0.f);
        }

        // ---- GEMM2: o[4c..4c+3] ----
        float o0 = sBb[4 * c + 0], o1 = sBb[4 * c + 1];
        float o2 = sBb[4 * c + 2], o3 = sBb[4 * c + 3];
        #pragma unroll
        for (int j = 0; j < 32; j++) {
            float tj;
            switch (j & 3) {
                case 0: tj = t0; break;
                case 1: tj = t1; break;
                case 2: tj = t2; break;
                default: tj = t3; break;
            }
            tj = __shfl_sync(FULL, tj, j >> 2, 8);
            float4 w = ((const float4*)&sW2[j * 32])[c];
            o0 = fmaf(tj, w.x, o0);
            o1 = fmaf(tj, w.y, o1);
            o2 = fmaf(tj, w.z, o2);
            o3 = fmaf(tj, w.w, o3);
        }
        o4 = make_float4(fmaxf(o0, 0.f), fmaxf(o1, 0.f),
                         fmaxf(o2, 0.f), fmaxf(o3, 0.f));
        fout[(size_t)node * 8 + c] = o4;
    } else {
        // inactive lanes still participate in GEMM shuffles harmlessly? No —
        // they skipped them (inside if). Only stats shuffles below are shared.
    }

    // ---- fused stats (per-column sum / sumsq) ----
    float s0 = o4.x, s1 = o4.y, s2 = o4.z, s3 = o4.w;
    float q0 = s0 * s0, q1 = s1 * s1, q2 = s2 * s2, q3 = s3 * s3;
    #pragma unroll
    for (int d = 8; d <= 16; d <<= 1) {
        s0 += __shfl_xor_sync(FULL, s0, d);
        s1 += __shfl_xor_sync(FULL, s1, d);
        s2 += __shfl_xor_sync(FULL, s2, d);
        s3 += __shfl_xor_sync(FULL, s3, d);
        q0 += __shfl_xor_sync(FULL, q0, d);
        q1 += __shfl_xor_sync(FULL, q1, d);
        q2 += __shfl_xor_sync(FULL, q2, d);
        q3 += __shfl_xor_sync(FULL, q3, d);
    }
    if ((tid & 31) < 8) {
        atomicAdd(&sstat[4 * c + 0], s0);
        atomicAdd(&sstat[4 * c + 1], s1);
        atomicAdd(&sstat[4 * c + 2], s2);
        atomicAdd(&sstat[4 * c + 3], s3);
        atomicAdd(&sstat[32 + 4 * c + 0], q0);
        atomicAdd(&sstat[32 + 4 * c + 1], q1);
        atomicAdd(&sstat[32 + 4 * c + 2], q2);
        atomicAdd(&sstat[32 + 4 * c + 3], q3);
    }
    __syncthreads();
    if (tid < 64) atomicAdd(&g_stats[layer * 64 + tid], sstat[tid]);
}

// ---------------- finalize: BN coeffs (+fold into next Wa) ------------------
__global__ void finalize_kernel(int l, const float* __restrict__ bn_g,
                                const float* __restrict__ bn_b,
                                const float* __restrict__ WaNext, int fold) {
    __shared__ float sa[32], sb[32];
    int tid = threadIdx.x;
    if (tid < 32) {
        float sum = g_stats[l * 64 + tid];
        float sq  = g_stats[l * 64 + 32 + tid];
        const float invN = 1.f / (float)NN;
        float mu  = sum * invN;
        float var = fmaxf(sq * invN - mu * mu, 0.f);
        float a = bn_g[l * 32 + tid] * rsqrtf(var + BN_EPS);
        float b = bn_b[l * 32 + tid] - mu * a;
        g_ab[tid] = a; g_ab[32 + tid] = b;
        sa[tid] = a; sb[tid] = b;
    }
    __syncthreads();
    if (tid < 64) g_stats[l * 64 + tid] = 0.f;
    if (fold) {
        int j = tid >> 5;
        g_Wap[tid] = sa[j] * WaNext[tid];
        if (tid < 32) {
            float cc = 0.f;
            #pragma unroll
            for (int j2 = 0; j2 < 32; j2++)
                cc = fmaf(sb[j2], WaNext[j2 * 32 + tid], cc);
            g_cvec[tid] = cc;
        }
    }
}

// ---------------- global add pool (lazy BN on final h, in bufB) -------------
__global__ void pool_kernel(const int* __restrict__ batch) {
    int tid = blockIdx.x * blockDim.x + threadIdx.x;
    if (tid >= NN * 8) return;
    int n = tid >> 3, c = tid & 7;
    float4 v = ((const float4*)g_bufB)[(size_t)n * 8 + c];
    int col = c * 4;
    v.x = fmaf(v.x, g_ab[col + 0], g_ab[32 + col + 0]);
    v.y = fmaf(v.y, g_ab[col + 1], g_ab[32 + col + 1]);
    v.z = fmaf(v.z, g_ab[col + 2], g_ab[32 + col + 2]);
    v.w = fmaf(v.w, g_ab[col + 3], g_ab[32 + col + 3]);
    int g = batch[n];
    red_add_f32x4(&g_pool[g * 8 + c], v);
}

// ---------------- head ------------------------------------------------------
__global__ void head_kernel(const float* __restrict__ fc1w, const float* __restrict__ fc1b,
                            const float* __restrict__ fc2w, const float* __restrict__ fc2b,
                            float* __restrict__ out) {
    int g = threadIdx.x;
    if (g >= 64) return;
    float in[32];
    #pragma unroll
    for (int j = 0; j < 8; j++) {
        float4 v = g_pool[g * 8 + j];
        in[4*j+0] = v.x; in[4*j+1] = v.y; in[4*j+2] = v.z; in[4*j+3] = v.w;
    }
    float t[32];
    #pragma unroll
    for (int k = 0; k < 32; k++) t[k] = fc1b[k];
    #pragma unroll
    for (int j = 0; j < 32; j++) {
        float xv = in[j];
        #pragma unroll
        for (int k = 0; k < 32; k++) t[k] = fmaf(xv, fc1w[j * 32 + k], t[k]);
    }
    #pragma unroll
    for (int k = 0; k < 32; k++) t[k] = fmaxf(t[k], 0.f);
    float o[10];
    #pragma unroll
    for (int c = 0; c < 10; c++) o[c] = fc2b[c];
    #pragma unroll
    for (int j = 0; j < 32; j++) {
        float xv = t[j];
        #pragma unroll
        for (int c = 0; c < 10; c++) o[c] = fmaf(xv, fc2w[j * 10 + c], o[c]);
    }
    #pragma unroll
    for (int c = 0; c < 10; c++) out[g * 10 + c] = o[c];
}

// ---------------- launch ----------------------------------------------------
extern "C" void kernel_launch(void* const* d_in, const int* in_sizes, int n_in,
                              void* d_out, int out_size) {
    const float* x     = (const float*)d_in[0];
    const int*   ei    = (const int*)d_in[1];
    const int*   batch = (const int*)d_in[2];
    const float* w1a = (const float*)d_in[3];
    const float* b1a = (const float*)d_in[4];
    const float* w1b = (const float*)d_in[5];
    const float* b1b = (const float*)d_in[6];
    const float* Wa  = (const float*)d_in[7];
    const float* Ba  = (const float*)d_in[8];
    const float* Wb  = (const float*)d_in[9];
    const float* Bb  = (const float*)d_in[10];
    const float* bng = (const float*)d_in[11];
    const float* bnb = (const float*)d_in[12];
    const float* fc1w = (const float*)d_in[13];
    const float* fc1b = (const float*)d_in[14];
    const float* fc2w = (const float*)d_in[15];
    const float* fc2b = (const float*)d_in[16];
    float* out = (float*)d_out;

    const int* srcs = ei;
    const int* dsts = ei + NE;

    const int LAYER_GRID = (NN + 63) / 64;   // 1563

    // launches 1-5: CSR build + proj
    combo_kernel<<<CNT_BLKS + PROJ_BLKS, 256>>>((const float2*)x, w1a, dsts);
    scan_a_kernel<<<N_SCAN_BLKS, 256>>>();
    scan_b_kernel<<<1, 128>>>();
    scan_c_kernel<<<(NN + 255) / 256, 256>>>();
    fill_kernel<<<(NE + 255) / 256, 256>>>(srcs, dsts);

    // layer 1 (fused, launch 6 -> profiled)
    layer_kernel<true><<<LAYER_GRID, 512>>>(w1b, b1a, b1b, 0);
    finalize_kernel<<<1, 1024>>>(0, bng, bnb, Wa, 1);

    // layers 2-5
    for (int i = 0; i < 4; i++) {
        layer_kernel<false><<<LAYER_GRID, 512>>>(Wb + i * 1024, Ba + i * 32,
                                                 Bb + i * 32, i + 1);
        int fold = (i < 3) ? 1 : 0;
        const float* WaNext = fold ? (Wa + (i + 1) * 1024) : Wa;
        finalize_kernel<<<1, 1024>>>(i + 1, bng, bnb, WaNext, fold);
    }

    pool_kernel<<<(NN * 8 + 255) / 256, 256>>>(batch);
    head_kernel<<<1, 64>>>(fc1w, fc1b, fc2w, fc2b, out);
}

// round 9
// speedup vs baseline: 1.1529x; 1.1529x over previous
#include <cuda_runtime.h>
#include <cuda_fp16.h>

#define NN 100000
#define NE 1600000
#define BN_EPS 1e-5f
#define SCAN_BLK 1024
#define N_SCAN_BLKS ((NN + SCAN_BLK - 1) / SCAN_BLK)   // 98
#define FULL 0xffffffffu
#define CNT_BLKS ((NE + 255) / 256)                     // 6250
#define PROJ_BLKS ((NN + 7) / 8)                        // 12500

// ---------------- scratch (static device memory, no allocs) ----------------
__device__ float g_bufA[NN * 32];     // node features h (fp32)
__device__ float g_agg[NN * 32];      // gathered sums
__device__ float g_stats[5 * 64];     // zero-init; self-cleaned by finalize
__device__ float g_ab[64];            // BN a[32], b[32] (for pool)
__device__ float g_Wap[1024];         // folded Wa' = diag(a)*Wa
__device__ float g_cvec[32];          // c = b @ Wa
__device__ float4 g_pool[64 * 8];     // zeroed by combo each replay
// CSR
__device__ int g_cnt[NN];             // histogram -> cursor -> re-zeroed by gather
__device__ int g_excl[NN];
__device__ int g_bsum[128];
__device__ int g_boff[128];
__device__ int g_rs[NN + 1];
__device__ int g_col[NE];
__device__ int g_done;                // last-block ticket; self-resetting

__device__ __forceinline__ void red_add_f32x4(float4* addr, float4 v) {
    asm volatile("red.global.add.v4.f32 [%0], {%1, %2, %3, %4};"
                 :: "l"(addr), "f"(v.x), "f"(v.y), "f"(v.z), "f"(v.w)
                 : "memory");
}

// ---------------- launch 1: count + proj (p = x @ W1a) + zero pool ----------
__global__ __launch_bounds__(256) void combo_kernel(
    const float2* __restrict__ x2, const float* __restrict__ W1a,
    const int* __restrict__ dsts) {
    __shared__ float sW[2048];        // 64x32
    int tid = threadIdx.x;
    if (blockIdx.x < CNT_BLKS) {
        int e = blockIdx.x * 256 + tid;
        if (e < NE) atomicAdd(&g_cnt[dsts[e]], 1);
        if (blockIdx.x == 0) {
            float* p = (float*)g_pool;
            for (int i = tid; i < 64 * 8 * 4; i += 256) p[i] = 0.f;
        }
        return;
    }
    for (int i = tid; i < 2048; i += 256) sW[i] = W1a[i];
    __syncthreads();
    int lane = tid & 31, wid = tid >> 5;
    int node = (blockIdx.x - CNT_BLKS) * 8 + wid;
    if (node >= NN) return;
    float2 xv = x2[(size_t)node * 32 + lane];
    float t = 0.f;
    #pragma unroll
    for (int j = 0; j < 32; j++) {
        float bx = __shfl_sync(FULL, xv.x, j);
        float by = __shfl_sync(FULL, xv.y, j);
        t = fmaf(bx, sW[(2 * j) * 32 + lane], t);
        t = fmaf(by, sW[(2 * j + 1) * 32 + lane], t);
    }
    g_bufA[(size_t)node * 32 + lane] = t;
}

// ---------------- launch 2: fused scan (per-block + last-block finalize) ---
__global__ __launch_bounds__(256) void scan_ab_kernel() {
    __shared__ int wsum[8];
    __shared__ int slast;
    __shared__ int s[256];
    int base = blockIdx.x * SCAN_BLK + threadIdx.x * 4;
    int v0 = (base + 0 < NN) ? g_cnt[base + 0] : 0;
    int v1 = (base + 1 < NN) ? g_cnt[base + 1] : 0;
    int v2 = (base + 2 < NN) ? g_cnt[base + 2] : 0;
    int v3 = (base + 3 < NN) ? g_cnt[base + 3] : 0;
    if (base + 0 < NN) g_cnt[base + 0] = 0;    // reset for use as fill cursor
    if (base + 1 < NN) g_cnt[base + 1] = 0;
    if (base + 2 < NN) g_cnt[base + 2] = 0;
    if (base + 3 < NN) g_cnt[base + 3] = 0;
    int tsum = v0 + v1 + v2 + v3;
    int lane = threadIdx.x & 31, wid = threadIdx.x >> 5;
    int incl = tsum;
    #pragma unroll
    for (int off = 1; off < 32; off <<= 1) {
        int n = __shfl_up_sync(FULL, incl, off);
        if (lane >= off) incl += n;
    }
    if (lane == 31) wsum[wid] = incl;
    __syncthreads();
    if (wid == 0 && lane < 8) {
        int w = wsum[lane];
        #pragma unroll
        for (int off = 1; off < 8; off <<= 1) {
            int n = __shfl_up_sync(0xffu, w, off);
            if (lane >= off) w += n;
        }
        wsum[lane] = w;
    }
    __syncthreads();
    int off = (wid > 0 ? wsum[wid - 1] : 0) + incl - tsum;
    if (base + 0 < NN) g_excl[base + 0] = off;
    if (base + 1 < NN) g_excl[base + 1] = off + v0;
    if (base + 2 < NN) g_excl[base + 2] = off + v0 + v1;
    if (base + 3 < NN) g_excl[base + 3] = off + v0 + v1 + v2;
    if (threadIdx.x == 0) g_bsum[blockIdx.x] = wsum[7];

    // last-arriving block scans the 98 block sums
    __threadfence();
    if (threadIdx.x == 0) slast = atomicAdd(&g_done, 1);
    __syncthreads();
    if (slast == N_SCAN_BLKS - 1) {
        int t = threadIdx.x;
        int val = (t < N_SCAN_BLKS) ? g_bsum[t] : 0;
        s[t] = val;
        __syncthreads();
        #pragma unroll
        for (int o = 1; o < 256; o <<= 1) {
            int v = (t >= o) ? s[t - o] : 0;
            __syncthreads();
            s[t] += v;
            __syncthreads();
        }
        if (t < N_SCAN_BLKS) g_boff[t] = s[t] - val;
        if (t == 0) g_done = 0;
    }
}

// ---------------- launch 3: rs write + CSR fill (cursor = g_cnt, from 0) ---
__global__ __launch_bounds__(256) void fill_kernel(const int* __restrict__ srcs,
                                                   const int* __restrict__ dsts) {
    int e = blockIdx.x * 256 + threadIdx.x;
    if (e < NN) g_rs[e] = g_excl[e] + g_boff[e >> 10];
    if (e == NN) g_rs[NN] = NE;
    if (e >= NE) return;
    int d = dsts[e];
    int rs = g_excl[d] + g_boff[d >> 10];
    int pos = rs + atomicAdd(&g_cnt[d], 1);
    g_col[pos] = srcs[e];
}

// ---------------- gather: warp-per-node, 4 edges x 8 channels per iter ------
// agg[n] = h[n] + sum_{j in N(n)} h[j]; also re-zeroes g_cnt for next replay.
__global__ __launch_bounds__(256) void gather_kernel() {
    int gw = (blockIdx.x * 256 + threadIdx.x) >> 5;   // global warp = node
    int lane = threadIdx.x & 31;
    if (gw >= NN) return;
    int node = gw;
    int sub = lane >> 3;          // edge slot 0..3
    int c   = lane & 7;           // float4 channel
    if (lane == 0) g_cnt[node] = 0;
    const float4* fin = (const float4*)g_bufA;
    int e0 = g_rs[node], e1 = g_rs[node + 1];

    float4 acc = (sub == 0) ? fin[(size_t)node * 8 + c]
                            : make_float4(0.f, 0.f, 0.f, 0.f);
    int e = e0 + sub;
    // 2x unrolled: 8 independent row loads in flight per warp iteration
    for (; e + 4 < e1; e += 8) {
        int s0 = __ldg(&g_col[e]);
        int s1 = __ldg(&g_col[e + 4]);
        float4 v0 = fin[(size_t)s0 * 8 + c];
        float4 v1 = fin[(size_t)s1 * 8 + c];
        acc.x += v0.x + v1.x; acc.y += v0.y + v1.y;
        acc.z += v0.z + v1.z; acc.w += v0.w + v1.w;
    }
    if (e < e1) {
        int s = __ldg(&g_col[e]);
        float4 v = fin[(size_t)s * 8 + c];
        acc.x += v.x; acc.y += v.y; acc.z += v.z; acc.w += v.w;
    }
    // reduce across 4 edge-subgroups (lanes differing in bits 3,4)
    acc.x += __shfl_xor_sync(FULL, acc.x, 8);
    acc.y += __shfl_xor_sync(FULL, acc.y, 8);
    acc.z += __shfl_xor_sync(FULL, acc.z, 8);
    acc.w += __shfl_xor_sync(FULL, acc.w, 8);
    acc.x += __shfl_xor_sync(FULL, acc.x, 16);
    acc.y += __shfl_xor_sync(FULL, acc.y, 16);
    acc.z += __shfl_xor_sync(FULL, acc.z, 16);
    acc.w += __shfl_xor_sync(FULL, acc.w, 16);
    if (lane < 8)
        ((float4*)g_agg)[(size_t)node * 8 + lane] = acc;
}

// ---------------- MLP (+fused stats). FIRST: skip GEMM1 (pre-projected) ----
template<bool FIRST>
__global__ __launch_bounds__(128) void mlp_kernel(
    const float* __restrict__ Wb, const float* __restrict__ Ba,
    const float* __restrict__ Bb, int layer) {
    __shared__ float sW1[1024];
    __shared__ float sW2[1024];
    __shared__ float sBa[32], sBb[32], sC[32];
    __shared__ float sx[128 * 33];
    int tid = threadIdx.x;
    for (int i = tid; i < 1024; i += 128) {
        if (!FIRST) sW1[i] = g_Wap[i];
        sW2[i] = Wb[i];
    }
    if (tid < 32) {
        sBa[tid] = Ba[tid];
        sBb[tid] = Bb[tid];
        sC[tid] = FIRST ? 0.f : g_cvec[tid];
    }
    int node0 = blockIdx.x * 128;
    for (int idx = tid; idx < 128 * 8; idx += 128) {
        int row = idx >> 3, cc = idx & 7;
        if (node0 + row < NN) {
            float4 v = ((const float4*)g_agg)[(size_t)(node0 + row) * 8 + cc];
            float* d = &sx[row * 33 + cc * 4];
            d[0] = v.x; d[1] = v.y; d[2] = v.z; d[3] = v.w;
        }
    }
    __syncthreads();

    int node = node0 + tid;
    bool active = node < NN;
    float o[32];
    if (active) {
        const float* xr = &sx[tid * 33];
        float t[32];
        if (FIRST) {
            #pragma unroll
            for (int k = 0; k < 32; k++) t[k] = fmaxf(xr[k] + sBa[k], 0.f);
        } else {
            float cnt = (float)(g_rs[node + 1] - g_rs[node] + 1);
            #pragma unroll
            for (int k = 0; k < 32; k++) t[k] = fmaf(cnt, sC[k], sBa[k]);
            #pragma unroll
            for (int j = 0; j < 32; j++) {
                float xv = xr[j];
                #pragma unroll
                for (int k = 0; k < 32; k++) t[k] = fmaf(xv, sW1[j * 32 + k], t[k]);
            }
            #pragma unroll
            for (int k = 0; k < 32; k++) t[k] = fmaxf(t[k], 0.f);
        }
        #pragma unroll
        for (int k = 0; k < 32; k++) o[k] = sBb[k];
        #pragma unroll
        for (int j = 0; j < 32; j++) {
            float tj = t[j];
            #pragma unroll
            for (int k = 0; k < 32; k++) o[k] = fmaf(tj, sW2[j * 32 + k], o[k]);
        }
        #pragma unroll
        for (int k = 0; k < 32; k++) o[k] = fmaxf(o[k], 0.f);
    } else {
        #pragma unroll
        for (int k = 0; k < 32; k++) o[k] = 0.f;
    }
    __syncthreads();
    {
        float* xr = &sx[tid * 33];
        #pragma unroll
        for (int k = 0; k < 32; k++) xr[k] = o[k];
    }
    __syncthreads();
    for (int idx = tid; idx < 128 * 8; idx += 128) {
        int row = idx >> 3, cc = idx & 7;
        if (node0 + row < NN) {
            const float* s = &sx[row * 33 + cc * 4];
            ((float4*)g_bufA)[(size_t)(node0 + row) * 8 + cc] =
                make_float4(s[0], s[1], s[2], s[3]);
        }
    }
    if (tid < 64) {
        int col = tid & 31;
        bool sq = tid >= 32;
        float s = 0.f;
        for (int r = 0; r < 128; r++) {
            float v = sx[r * 33 + col];
            s += sq ? v * v : v;
        }
        atomicAdd(&g_stats[layer * 64 + (sq ? 32 : 0) + col], s);
    }
}

// ---------------- finalize: BN coeffs (+fold into next Wa) ------------------
__global__ void finalize_kernel(int l, const float* __restrict__ bn_g,
                                const float* __restrict__ bn_b,
                                const float* __restrict__ WaNext, int fold) {
    __shared__ float sa[32], sb[32];
    int tid = threadIdx.x;
    if (tid < 32) {
        float sum = g_stats[l * 64 + tid];
        float sq  = g_stats[l * 64 + 32 + tid];
        const float invN = 1.f / (float)NN;
        float mu  = sum * invN;
        float var = fmaxf(sq * invN - mu * mu, 0.f);
        float a = bn_g[l * 32 + tid] * rsqrtf(var + BN_EPS);
        float b = bn_b[l * 32 + tid] - mu * a;
        g_ab[tid] = a; g_ab[32 + tid] = b;
        sa[tid] = a; sb[tid] = b;
    }
    __syncthreads();
    if (tid < 64) g_stats[l * 64 + tid] = 0.f;
    if (fold) {
        int j = tid >> 5;
        g_Wap[tid] = sa[j] * WaNext[tid];
        if (tid < 32) {
            float cc = 0.f;
            #pragma unroll
            for (int j2 = 0; j2 < 32; j2++)
                cc = fmaf(sb[j2], WaNext[j2 * 32 + tid], cc);
            g_cvec[tid] = cc;
        }
    }
}

// ---------------- global add pool (lazy BN on final h) ----------------------
__global__ void pool_kernel(const int* __restrict__ batch) {
    int tid = blockIdx.x * blockDim.x + threadIdx.x;
    if (tid >= NN * 8) return;
    int n = tid >> 3, c = tid & 7;
    float4 v = ((const float4*)g_bufA)[(size_t)n * 8 + c];
    int col = c * 4;
    v.x = fmaf(v.x, g_ab[col + 0], g_ab[32 + col + 0]);
    v.y = fmaf(v.y, g_ab[col + 1], g_ab[32 + col + 1]);
    v.z = fmaf(v.z, g_ab[col + 2], g_ab[32 + col + 2]);
    v.w = fmaf(v.w, g_ab[col + 3], g_ab[32 + col + 3]);
    int g = batch[n];
    red_add_f32x4(&g_pool[g * 8 + c], v);
}

// ---------------- head ------------------------------------------------------
__global__ void head_kernel(const float* __restrict__ fc1w, const float* __restrict__ fc1b,
                            const float* __restrict__ fc2w, const float* __restrict__ fc2b,
                            float* __restrict__ out) {
    int g = threadIdx.x;
    if (g >= 64) return;
    float in[32];
    #pragma unroll
    for (int j = 0; j < 8; j++) {
        float4 v = g_pool[g * 8 + j];
        in[4*j+0] = v.x; in[4*j+1] = v.y; in[4*j+2] = v.z; in[4*j+3] = v.w;
    }
    float t[32];
    #pragma unroll
    for (int k = 0; k < 32; k++) t[k] = fc1b[k];
    #pragma unroll
    for (int j = 0; j < 32; j++) {
        float xv = in[j];
        #pragma unroll
        for (int k = 0; k < 32; k++) t[k] = fmaf(xv, fc1w[j * 32 + k], t[k]);
    }
    #pragma unroll
    for (int k = 0; k < 32; k++) t[k] = fmaxf(t[k], 0.f);
    float o[10];
    #pragma unroll
    for (int c = 0; c < 10; c++) o[c] = fc2b[c];
    #pragma unroll
    for (int j = 0; j < 32; j++) {
        float xv = t[j];
        #pragma unroll
        for (int c = 0; c < 10; c++) o[c] = fmaf(xv, fc2w[j * 10 + c], o[c]);
    }
    #pragma unroll
    for (int c = 0; c < 10; c++) out[g * 10 + c] = o[c];
}

// ---------------- launch ----------------------------------------------------
extern "C" void kernel_launch(void* const* d_in, const int* in_sizes, int n_in,
                              void* d_out, int out_size) {
    const float* x     = (const float*)d_in[0];
    const int*   ei    = (const int*)d_in[1];
    const int*   batch = (const int*)d_in[2];
    const float* w1a = (const float*)d_in[3];
    const float* b1a = (const float*)d_in[4];
    const float* w1b = (const float*)d_in[5];
    const float* b1b = (const float*)d_in[6];
    const float* Wa  = (const float*)d_in[7];
    const float* Ba  = (const float*)d_in[8];
    const float* Wb  = (const float*)d_in[9];
    const float* Bb  = (const float*)d_in[10];
    const float* bng = (const float*)d_in[11];
    const float* bnb = (const float*)d_in[12];
    const float* fc1w = (const float*)d_in[13];
    const float* fc1b = (const float*)d_in[14];
    const float* fc2w = (const float*)d_in[15];
    const float* fc2b = (const float*)d_in[16];
    float* out = (float*)d_out;

    const int* srcs = ei;
    const int* dsts = ei + NE;

    const int GATHER_GRID = (NN * 32 + 255) / 256;  // warp per node: 12500
    const int MLP_GRID = (NN + 127) / 128;          // 782

    // launches 1-3: CSR build + proj
    combo_kernel<<<CNT_BLKS + PROJ_BLKS, 256>>>((const float2*)x, w1a, dsts);
    scan_ab_kernel<<<N_SCAN_BLKS, 256>>>();
    fill_kernel<<<(NE + 255) / 256, 256>>>(srcs, dsts);

    // layer 1 (launch 4 = gather -> profiled)
    gather_kernel<<<GATHER_GRID, 256>>>();
    mlp_kernel<true><<<MLP_GRID, 128>>>(w1b, b1a, b1b, 0);
    finalize_kernel<<<1, 1024>>>(0, bng, bnb, Wa, 1);

    // layers 2-5
    for (int i = 0; i < 4; i++) {
        gather_kernel<<<GATHER_GRID, 256>>>();
        mlp_kernel<false><<<MLP_GRID, 128>>>(Wb + i * 1024, Ba + i * 32,
                                             Bb + i * 32, i + 1);
        int fold = (i < 3) ? 1 : 0;
        const float* WaNext = fold ? (Wa + (i + 1) * 1024) : Wa;
        finalize_kernel<<<1, 1024>>>(i + 1, bng, bnb, WaNext, fold);
    }

    pool_kernel<<<(NN * 8 + 255) / 256, 256>>>(batch);
    head_kernel<<<1, 64>>>(fc1w, fc1b, fc2w, fc2b, out);
}